// round 7
// baseline (speedup 1.0000x reference)
#include <cuda_runtime.h>
#include <math_constants.h>
#include <stdint.h>

// PQHead: out[b, m*6+d] = codebooks[m, argmax_k <x[b,m*6:...], cb[m,k,:]>, d]
// (forward value of the straight-through estimator == discrete codeword)
//
// FROZEN NUMERICS: each dot is mul.rn(x0,c0) then fma.rn chain d=1..5, and the
// argmax is an exact strict-'>' predicated compare (first-max tie rule). The
// f32x2 packing below packs TWO ROWS per instruction -- each component is the
// identical scalar chain, bit-exact. Zero argmax flips vs the JAX reference.
//
// CONFIG LESSONS:
//  R3/R4: reg cap + full k-unroll -> spills -> 8x DRAM, issue 15%.
//  R5/R6: unroll-4 bound, 61 regs, 4 CTAs/SM -> issue 65%, issue-COUNT bound.
//  R7: halve fma-pipe issues with packed f32x2 FMA (rows packed, not dims).

#define B_ROWS   32768
#define M_SUB    128
#define QM       16                      // m's per block (1/8 split)
#define NGRP     (M_SUB / QM)            // 8 m-groups
#define K_CODES  32
#define D_SUB    6
#define DIM      768
#define RPT      4                       // rows per thread (2 packed pairs)
#define TPB      256                     // 16 row-groups x 16 m
#define TILE_ROWS (RPT * (TPB / QM))     // 64
#define NTILES   (B_ROWS / TILE_ROWS)    // 512 per group
#define BLK_PER_G 74                     // 8 groups x 74 = 592 = 4/SM
#define NBLOCKS  (NGRP * BLK_PER_G)
#define CB_WORDS (QM * K_CODES * D_SUB)  // 3072 x 8B = 24KB (duplicated pairs)

__device__ __forceinline__ unsigned long long pk2(float lo, float hi) {
    unsigned long long r;
    asm("mov.b64 %0, {%1, %2};" : "=l"(r) : "f"(lo), "f"(hi));
    return r;
}

__global__ void __launch_bounds__(TPB, 4)
pq_head_kernel(const float* __restrict__ x,
               const float* __restrict__ cb,
               float* __restrict__ out)
{
    // cbs[(k*6+d)*16 + m] = (c, c) duplicated pair -> broadcast LDS.64 feeds
    // fma.rn.f32x2 directly, no per-k packing movs.
    __shared__ float2 cbs[CB_WORDS];

    const int t = threadIdx.x;
    const int grp = blockIdx.x / BLK_PER_G;      // which m-group this block owns
    const int bstart = blockIdx.x % BLK_PER_G;

    // One-time codebook load for this group (coalesced global, duplicated smem).
    {
        const float* cbg = cb + (size_t)grp * QM * (K_CODES * D_SUB);
        for (int i = t; i < CB_WORDS; i += TPB) {
            int mloc = i / (K_CODES * D_SUB);    // 192 floats per m
            int kd   = i - mloc * (K_CODES * D_SUB);
            float c = cbg[(size_t)mloc * (K_CODES * D_SUB) + kd];
            cbs[kd * QM + mloc] = make_float2(c, c);
        }
    }
    __syncthreads();

    const int mloc = t & (QM - 1);
    const int g    = t >> 4;             // row-group 0..15
    const int col0 = (grp * QM + mloc) * D_SUB;

    for (int tile = bstart; tile < NTILES; tile += BLK_PER_G) {
        const int b0 = tile * TILE_ROWS + g * RPT;

        // Load RPT rows' subvectors and pack row-pairs: xp[p][d] = (row2p, row2p+1).
        unsigned long long xp[RPT / 2][D_SUB];
        #pragma unroll
        for (int p = 0; p < RPT / 2; p++) {
            const float2* p0 = reinterpret_cast<const float2*>(
                x + (size_t)(b0 + 2 * p) * DIM + col0);
            const float2* p1 = reinterpret_cast<const float2*>(
                x + (size_t)(b0 + 2 * p + 1) * DIM + col0);
            float2 a0 = p0[0], b0v = p0[1], c0v = p0[2];
            float2 a1 = p1[0], b1v = p1[1], c1v = p1[2];
            xp[p][0] = pk2(a0.x, a1.x);  xp[p][1] = pk2(a0.y, a1.y);
            xp[p][2] = pk2(b0v.x, b1v.x); xp[p][3] = pk2(b0v.y, b1v.y);
            xp[p][4] = pk2(c0v.x, c1v.x); xp[p][5] = pk2(c0v.y, c1v.y);
        }

        float best[RPT];
        int   idx[RPT];
        #pragma unroll
        for (int r = 0; r < RPT; r++) { best[r] = -CUDART_INF_F; idx[r] = 0; }

        // Bounded unroll keeps the live set under the 64-reg cap (no spills).
        #pragma unroll 4
        for (int k = 0; k < K_CODES; k++) {
            const unsigned long long* cw =
                reinterpret_cast<const unsigned long long*>(&cbs[k * D_SUB * QM]);
            unsigned long long c0 = cw[0 * QM + mloc];
            unsigned long long c1 = cw[1 * QM + mloc];
            unsigned long long c2 = cw[2 * QM + mloc];
            unsigned long long c3 = cw[3 * QM + mloc];
            unsigned long long c4 = cw[4 * QM + mloc];
            unsigned long long c5 = cw[5 * QM + mloc];
            #pragma unroll
            for (int p = 0; p < RPT / 2; p++) {
                unsigned long long acc;
                // Component-wise: mul.rn then 5x fma.rn -- the frozen scalar chain.
                asm("mul.rn.f32x2 %0, %1, %2;"
                    : "=l"(acc) : "l"(xp[p][0]), "l"(c0));
                asm("fma.rn.f32x2 %0, %1, %2, %0;" : "+l"(acc) : "l"(xp[p][1]), "l"(c1));
                asm("fma.rn.f32x2 %0, %1, %2, %0;" : "+l"(acc) : "l"(xp[p][2]), "l"(c2));
                asm("fma.rn.f32x2 %0, %1, %2, %0;" : "+l"(acc) : "l"(xp[p][3]), "l"(c3));
                asm("fma.rn.f32x2 %0, %1, %2, %0;" : "+l"(acc) : "l"(xp[p][4]), "l"(c4));
                asm("fma.rn.f32x2 %0, %1, %2, %0;" : "+l"(acc) : "l"(xp[p][5]), "l"(c5));
                float dlo, dhi;
                asm("mov.b64 {%0, %1}, %2;" : "=f"(dlo), "=f"(dhi) : "l"(acc));
                // EXACT argmax; strict '>' keeps the FIRST max (jnp tie rule).
                bool plo = dlo > best[2 * p];
                best[2 * p]     = plo ? dlo : best[2 * p];
                idx[2 * p]      = plo ? k   : idx[2 * p];
                bool phi = dhi > best[2 * p + 1];
                best[2 * p + 1] = phi ? dhi : best[2 * p + 1];
                idx[2 * p + 1]  = phi ? k   : idx[2 * p + 1];
            }
        }

        // Emit the winning codeword rows (duplicated pairs: take .x).
        #pragma unroll
        for (int r = 0; r < RPT; r++) {
            const float2* crow = &cbs[idx[r] * D_SUB * QM];
            float o0 = crow[0 * QM + mloc].x;
            float o1 = crow[1 * QM + mloc].x;
            float o2 = crow[2 * QM + mloc].x;
            float o3 = crow[3 * QM + mloc].x;
            float o4 = crow[4 * QM + mloc].x;
            float o5 = crow[5 * QM + mloc].x;
            float2* po = reinterpret_cast<float2*>(
                out + (size_t)(b0 + r) * DIM + col0);
            po[0] = make_float2(o0, o1);
            po[1] = make_float2(o2, o3);
            po[2] = make_float2(o4, o5);
        }
    }
}

extern "C" void kernel_launch(void* const* d_in, const int* in_sizes, int n_in,
                              void* d_out, int out_size)
{
    const float* x  = (const float*)d_in[0];
    const float* cb = (const float*)d_in[1];
    float* out      = (float*)d_out;

    pq_head_kernel<<<NBLOCKS, TPB>>>(x, cb, out);
}

// round 8
// speedup vs baseline: 1.3457x; 1.3457x over previous
#include <cuda_runtime.h>
#include <math_constants.h>
#include <stdint.h>

// PQHead: out[b, m*6+d] = codebooks[m, argmax_k <x[b,m*6:...], cb[m,k,:]>, d]
// (forward value of the straight-through estimator == discrete codeword)
//
// FROZEN NUMERICS: dot = x0*c0 then fma.rn chain d=1..5 (scalar FFMA), argmax
// exact with FIRST-max tie rule. Zero flips vs JAX reference at this order.
//
// CONFIG LESSONS:
//  R3/R4: reg cap + FULL k-unroll -> spills -> 8x DRAM, issue 15%.
//  R5/R6: unroll-4 bound, 61 regs, 4 CTAs/SM (32 warps) -> 66.7us, issue 65%.
//  R7: fma.rn.f32x2 is HALF-RATE on sm_103a fma pipe + mov tax -> regression.
//  R8: trim LDS (float4+float2 cb split), FMNMX value chain (pred off the
//      loop-carried path), pointer-increment addressing.

#define B_ROWS   32768
#define M_SUB    128
#define QM       16                      // m's per block (1/8 split)
#define NGRP     (M_SUB / QM)            // 8
#define K_CODES  32
#define D_SUB    6
#define DIM      768
#define RPT      4                       // rows per thread
#define TPB      256                     // 16 row-groups x 16 m
#define TILE_ROWS (RPT * (TPB / QM))     // 64
#define NTILES   (B_ROWS / TILE_ROWS)    // 512 per group
#define BLK_PER_G 74                     // 8 groups x 74 = 592 = 4/SM
#define NBLOCKS  (NGRP * BLK_PER_G)

__global__ void __launch_bounds__(TPB, 4)
pq_head_kernel(const float* __restrict__ x,
               const float* __restrict__ cb,
               float* __restrict__ out)
{
    // Codebook split: cbA[k*16+m] = (d0,d1,d2,d3), cbB[k*16+m] = (d4,d5).
    // 16 lanes x 16B = 256B per half-warp phase, lanes 16-31 broadcast the
    // same addresses -> conflict-free. 12KB total per CTA.
    __shared__ float4 cbA[K_CODES * QM];     // 8KB
    __shared__ float2 cbB[K_CODES * QM];     // 4KB

    const int t = threadIdx.x;
    const int grp = blockIdx.x / BLK_PER_G;      // which m-group this block owns
    const int bstart = blockIdx.x % BLK_PER_G;

    // One-time codebook load for this group.
    {
        const float* cbg = cb + (size_t)grp * QM * (K_CODES * D_SUB);
        for (int i = t; i < QM * K_CODES; i += TPB) {
            int mloc = i / K_CODES;
            int k    = i - mloc * K_CODES;
            const float* src = cbg + (size_t)mloc * (K_CODES * D_SUB) + k * D_SUB;
            cbA[k * QM + mloc] = make_float4(src[0], src[1], src[2], src[3]);
            cbB[k * QM + mloc] = make_float2(src[4], src[5]);
        }
    }
    __syncthreads();

    const int mloc = t & (QM - 1);
    const int g    = t >> 4;             // row-group 0..15
    const int col0 = (grp * QM + mloc) * D_SUB;

    // Running pointers (advance by BLK_PER_G tiles each iteration).
    const float* xp = x   + (size_t)(bstart * TILE_ROWS + g * RPT) * DIM + col0;
    float*       op = out + (size_t)(bstart * TILE_ROWS + g * RPT) * DIM + col0;
    const size_t step = (size_t)BLK_PER_G * TILE_ROWS * DIM;

    for (int tile = bstart; tile < NTILES; tile += BLK_PER_G) {
        // Batch-load RPT rows' 6-float subvectors (3x LDG.64 each, front-loaded).
        float xv[RPT][D_SUB];
        #pragma unroll
        for (int r = 0; r < RPT; r++) {
            const float2* p = reinterpret_cast<const float2*>(xp + (size_t)r * DIM);
            float2 a = p[0], bq = p[1], c = p[2];
            xv[r][0] = a.x;  xv[r][1] = a.y;
            xv[r][2] = bq.x; xv[r][3] = bq.y;
            xv[r][4] = c.x;  xv[r][5] = c.y;
        }

        float best[RPT];
        int   idx[RPT];
        #pragma unroll
        for (int r = 0; r < RPT; r++) { best[r] = -CUDART_INF_F; idx[r] = 0; }

        // Bounded unroll keeps live set ~61 regs (no spills).
        #pragma unroll 4
        for (int k = 0; k < K_CODES; k++) {
            const float4 ca = cbA[k * QM + mloc];
            const float2 cbv = cbB[k * QM + mloc];
            #pragma unroll
            for (int r = 0; r < RPT; r++) {
                float dot = xv[r][0] * ca.x;
                dot = fmaf(xv[r][1], ca.y, dot);
                dot = fmaf(xv[r][2], ca.z, dot);
                dot = fmaf(xv[r][3], ca.w, dot);
                dot = fmaf(xv[r][4], cbv.x, dot);
                dot = fmaf(xv[r][5], cbv.y, dot);
                // EXACT argmax, FIRST-max tie rule. Value chain via FMNMX
                // (no predicate); only the idx SEL consumes the predicate,
                // and idx is not read until emit -> pred latency hidden.
                bool p  = dot > best[r];
                best[r] = fmaxf(best[r], dot);
                idx[r]  = p ? k : idx[r];
            }
        }

        // Emit the winning codeword rows.
        #pragma unroll
        for (int r = 0; r < RPT; r++) {
            const float4 oa = cbA[idx[r] * QM + mloc];
            const float2 ob = cbB[idx[r] * QM + mloc];
            float2* po = reinterpret_cast<float2*>(op + (size_t)r * DIM);
            po[0] = make_float2(oa.x, oa.y);
            po[1] = make_float2(oa.z, oa.w);
            po[2] = ob;
        }

        xp += step;
        op += step;
    }
}

extern "C" void kernel_launch(void* const* d_in, const int* in_sizes, int n_in,
                              void* d_out, int out_size)
{
    const float* x  = (const float*)d_in[0];
    const float* cb = (const float*)d_in[1];
    float* out      = (float*)d_out;

    pq_head_kernel<<<NBLOCKS, TPB>>>(x, cb, out);
}

// round 9
// speedup vs baseline: 1.3964x; 1.0377x over previous
#include <cuda_runtime.h>
#include <math_constants.h>
#include <stdint.h>

// PQHead: out[b, m*6+d] = codebooks[m, argmax_k <x[b,m*6:...], cb[m,k,:]>, d]
// (forward value of the straight-through estimator == discrete codeword)
//
// FROZEN NUMERICS: dot = x0*c0 then fma.rn chain d=1..5 (scalar FFMA), argmax
// exact, FIRST-max tie rule. Zero flips vs JAX reference at this order.
//
// LESSONS:
//  R3/R4: reg cap + FULL k-unroll -> spills -> 8x DRAM, issue 15%.
//  R5/R6: unroll-4, 61 regs, 32 warps/SM -> 66.7us, issue 65%.
//  R7: fma.rn.f32x2 is half-rate on sm_103a -> regression. No f32x2.
//  R8: op-count trims changed issue% but NOT duration -> pin = per-tile
//      head stall on dependent x LDGs.
//  R9: cross-tile register prefetch of x hides the LDG latency.

#define B_ROWS   32768
#define M_SUB    128
#define QM       16                      // m's per block (1/8 split)
#define NGRP     (M_SUB / QM)            // 8
#define K_CODES  32
#define D_SUB    6
#define DIM      768
#define RPT      2                       // rows per thread (frees regs for prefetch)
#define TPB      256                     // 16 row-groups x 16 m
#define TILE_ROWS (RPT * (TPB / QM))     // 32
#define NTILES   (B_ROWS / TILE_ROWS)    // 1024 per group
#define BLK_PER_G 74                     // 8 groups x 74 = 592 = 4/SM
#define NBLOCKS  (NGRP * BLK_PER_G)

__global__ void __launch_bounds__(TPB, 4)
pq_head_kernel(const float* __restrict__ x,
               const float* __restrict__ cb,
               float* __restrict__ out)
{
    // Codebook split: cbA[k*16+m] = (d0,d1,d2,d3), cbB[k*16+m] = (d4,d5).
    // 16-lane pattern, upper half-warp broadcasts -> conflict-free. 12KB/CTA.
    __shared__ float4 cbA[K_CODES * QM];     // 8KB
    __shared__ float2 cbB[K_CODES * QM];     // 4KB

    const int t = threadIdx.x;
    const int grp = blockIdx.x / BLK_PER_G;      // which m-group this block owns
    const int bstart = blockIdx.x % BLK_PER_G;

    // One-time codebook load for this group.
    {
        const float* cbg = cb + (size_t)grp * QM * (K_CODES * D_SUB);
        for (int i = t; i < QM * K_CODES; i += TPB) {
            int mloc = i / K_CODES;
            int k    = i - mloc * K_CODES;
            const float* src = cbg + (size_t)mloc * (K_CODES * D_SUB) + k * D_SUB;
            cbA[k * QM + mloc] = make_float4(src[0], src[1], src[2], src[3]);
            cbB[k * QM + mloc] = make_float2(src[4], src[5]);
        }
    }
    __syncthreads();

    const int mloc = t & (QM - 1);
    const int g    = t >> 4;             // row-group 0..15
    const int col0 = (grp * QM + mloc) * D_SUB;

    const size_t step = (size_t)BLK_PER_G * TILE_ROWS * DIM;
    const float* xp = x   + (size_t)(bstart * TILE_ROWS + g * RPT) * DIM + col0;
    float*       op = out + (size_t)(bstart * TILE_ROWS + g * RPT) * DIM + col0;

    // Prologue: load first tile's subvectors.
    float xv[RPT][D_SUB];
    #pragma unroll
    for (int r = 0; r < RPT; r++) {
        const float2* p = reinterpret_cast<const float2*>(xp + (size_t)r * DIM);
        float2 a = p[0], bq = p[1], c = p[2];
        xv[r][0] = a.x;  xv[r][1] = a.y;
        xv[r][2] = bq.x; xv[r][3] = bq.y;
        xv[r][4] = c.x;  xv[r][5] = c.y;
    }

    for (int tile = bstart; tile < NTILES; tile += BLK_PER_G) {
        // ---- Prefetch next tile's x into registers (clamped on last tile).
        const float* nxp = (tile + BLK_PER_G < NTILES) ? (xp + step) : xp;
        float nx[RPT][D_SUB];
        #pragma unroll
        for (int r = 0; r < RPT; r++) {
            const float2* p = reinterpret_cast<const float2*>(nxp + (size_t)r * DIM);
            float2 a = p[0], bq = p[1], c = p[2];
            nx[r][0] = a.x;  nx[r][1] = a.y;
            nx[r][2] = bq.x; nx[r][3] = bq.y;
            nx[r][4] = c.x;  nx[r][5] = c.y;
        }

        // ---- Argmax over 32 codewords (compute hides the prefetch latency).
        float best[RPT];
        int   idx[RPT];
        #pragma unroll
        for (int r = 0; r < RPT; r++) { best[r] = -CUDART_INF_F; idx[r] = 0; }

        #pragma unroll 4
        for (int k = 0; k < K_CODES; k++) {
            const float4 ca  = cbA[k * QM + mloc];
            const float2 cbv = cbB[k * QM + mloc];
            #pragma unroll
            for (int r = 0; r < RPT; r++) {
                float dot = xv[r][0] * ca.x;
                dot = fmaf(xv[r][1], ca.y, dot);
                dot = fmaf(xv[r][2], ca.z, dot);
                dot = fmaf(xv[r][3], ca.w, dot);
                dot = fmaf(xv[r][4], cbv.x, dot);
                dot = fmaf(xv[r][5], cbv.y, dot);
                // EXACT argmax, FIRST-max tie rule; FMNMX value chain keeps
                // the 13-cyc predicate latency off the loop-carried path.
                bool p  = dot > best[r];
                best[r] = fmaxf(best[r], dot);
                idx[r]  = p ? k : idx[r];
            }
        }

        // ---- Emit the winning codeword rows.
        #pragma unroll
        for (int r = 0; r < RPT; r++) {
            const float4 oa = cbA[idx[r] * QM + mloc];
            const float2 ob = cbB[idx[r] * QM + mloc];
            float2* po = reinterpret_cast<float2*>(op + (size_t)r * DIM);
            po[0] = make_float2(oa.x, oa.y);
            po[1] = make_float2(oa.z, oa.w);
            po[2] = ob;
        }

        // ---- Rotate prefetched registers in.
        #pragma unroll
        for (int r = 0; r < RPT; r++)
            #pragma unroll
            for (int d = 0; d < D_SUB; d++)
                xv[r][d] = nx[r][d];

        xp = nxp;
        op += step;
    }
}

extern "C" void kernel_launch(void* const* d_in, const int* in_sizes, int n_in,
                              void* d_out, int out_size)
{
    const float* x  = (const float*)d_in[0];
    const float* cb = (const float*)d_in[1];
    float* out      = (float*)d_out;

    pq_head_kernel<<<NBLOCKS, TPB>>>(x, cb, out);
}